// round 14
// baseline (speedup 1.0000x reference)
#include <cuda_runtime.h>
#include <math.h>

#define NB   8
#define NN   512
#define FF   8
#define FP   16
#define NH1  64
#define NH2  32
#define NS   2
#define TIT  10
#define NBNN (NB*NN)

// ---------------- scratch (no allocations allowed) ----------------
__device__ __align__(256) float  g_A  [NB*NN*NH1];   // u_i @ W1a + sigma*w1s + b1
__device__ __align__(256) float4 g_Bv [16*NB*NN];    // u_j @ W1b, v-major planes
__device__ __align__(256) float  g_si [NB*NN];
__device__ __align__(256) float  g_sj [NB*NN];
__device__ __align__(256) float  g_mx [NB*NN];
__device__ __align__(256) float  g_invd[NB*NN];
__device__ __align__(256) float  g_gh [NB*NN*24];
__device__ __align__(256) float  g_u  [2][NB*NN*FF];
__device__ __align__(256) unsigned short g_nbr[NB*NN*NN];
__device__ __align__(256) float  g_ec [NB*NN*NN];
__device__ __align__(256) int    g_cnt[NB*NN];

__device__ __forceinline__ unsigned tf32r(float x) {
    unsigned r; asm("cvt.rna.tf32.f32 %0, %1;" : "=r"(r) : "f"(x)); return r;
}
__device__ __forceinline__ float tf32f(float x) {
    return __uint_as_float(tf32r(x));
}

#define MMA_TF32(d0,d1,d2,d3,a0,a1,a2,a3,b0,b1) \
  asm("mma.sync.aligned.m16n8k8.row.col.f32.tf32.tf32.f32 " \
      "{%0,%1,%2,%3},{%4,%5,%6,%7},{%8,%9},{%0,%1,%2,%3};" \
      : "+f"(d0),"+f"(d1),"+f"(d2),"+f"(d3) \
      : "r"(a0),"r"(a1),"r"(a2),"r"(a3),"r"(b0),"r"(b1))

// ---------------- adjacency compaction ----------------
__global__ void k_compact(const int* __restrict__ adj, const float* __restrict__ ef)
{
    int warp = (blockIdx.x * blockDim.x + threadIdx.x) >> 5;
    int lane = threadIdx.x & 31;
    if (warp >= NB*NN) return;
    const int*   arow = adj + (size_t)warp * NN;
    const float* erow = ef  + (size_t)warp * NN;
    int base = 0;
    #pragma unroll
    for (int c = 0; c < NN/32; c++) {
        int jj = c*32 + lane;
        int a  = arow[jj];
        unsigned bal = __ballot_sync(0xffffffffu, a > 0);
        if (a > 0) {
            int pos = base + __popc(bal & ((1u << lane) - 1u));
            g_nbr[(size_t)warp*NN + pos] = (unsigned short)jj;
            g_ec [(size_t)warp*NN + pos] = erow[jj];
        }
        base += __popc(bal);
    }
    if (lane == 0) g_cnt[warp] = base;
}

// ---------------- per-node precompute ----------------
__global__ void k_node(const float* __restrict__ u0,
                       const float* __restrict__ Wattn,
                       const float* __restrict__ al, const float* __restrict__ ar,
                       const float* __restrict__ W1, const float* __restrict__ b1,
                       const float* __restrict__ Whh, const float* __restrict__ bhh,
                       const float* __restrict__ sigma2, int t)
{
    __shared__ float sWa[FF*FP], sal[FP], sar[FP];
    __shared__ float sW1a[FF*NH1], sW1b[FF*NH1], sw1s[NH1], sb1[NH1];
    __shared__ float sWhh[FF*24], sbhh[24];
    int tid = threadIdx.x;
    for (int x = tid; x < FF*FP; x += blockDim.x) sWa[x] = Wattn[x];
    if (tid < FP) { sal[tid] = al[tid]; sar[tid] = ar[tid]; }
    for (int x = tid; x < FF*NH1; x += blockDim.x) {
        sW1a[x] = W1[x];
        sW1b[x] = W1[FF*NH1 + x];
    }
    if (tid < NH1) { sw1s[tid] = W1[17*NH1 + tid]; sb1[tid] = b1[tid]; }
    for (int x = tid; x < FF*24; x += blockDim.x) sWhh[x] = Whh[x];
    if (tid < 24) sbhh[tid] = bhh[tid];
    __syncthreads();

    int node = blockIdx.x * blockDim.x + tid;
    int b = node >> 9;
    const float* uin = (t == 0) ? u0 : g_u[t & 1];
    float u[FF];
    #pragma unroll
    for (int x = 0; x < FF; x++) u[x] = uin[node*FF + x];
    float sg = sigma2[b];

    float si = 0.f, sj = 0.f;
    #pragma unroll
    for (int p = 0; p < FP; p++) {
        float acc = 0.f;
        #pragma unroll
        for (int x = 0; x < FF; x++) acc = fmaf(u[x], sWa[x*FP + p], acc);
        si = fmaf(acc, sal[p], si);
        sj = fmaf(acc, sar[p], sj);
    }
    g_si[node] = si; g_sj[node] = sj;

    float bb[NH1];
    for (int m = 0; m < NH1; m++) {
        float a  = fmaf(sg, sw1s[m], sb1[m]);
        float b2 = 0.f;
        #pragma unroll
        for (int x = 0; x < FF; x++) {
            a  = fmaf(u[x], sW1a[x*NH1 + m], a);
            b2 = fmaf(u[x], sW1b[x*NH1 + m], b2);
        }
        g_A[(size_t)node*NH1 + m] = a;
        bb[m] = b2;
    }
    #pragma unroll
    for (int v = 0; v < 16; v++)
        g_Bv[v*NBNN + node] = make_float4(bb[4*v+0], bb[4*v+1], bb[4*v+2], bb[4*v+3]);

    for (int g = 0; g < 24; g++) {
        float acc = sbhh[g];
        #pragma unroll
        for (int x = 0; x < FF; x++) acc = fmaf(u[x], sWhh[x*24 + g], acc);
        g_gh[(size_t)node*24 + g] = acc;
    }
}

// ---------------- softmax stats per row ----------------
__global__ void k_soft()
{
    int warp = (blockIdx.x * blockDim.x + threadIdx.x) >> 5;
    int lane = threadIdx.x & 31;
    if (warp >= NB*NN) return;
    int b = warp >> 9;
    int cnt = g_cnt[warp];
    float si = g_si[warp];
    const unsigned short* nb = g_nbr + (size_t)warp*NN;
    const float* sjb = g_sj + b*NN;

    float mx = -3.4e38f;
    for (int s = lane; s < cnt; s += 32) {
        float bt = si + sjb[nb[s]];
        bt = bt > 0.f ? bt : 0.2f*bt;
        mx = fmaxf(mx, bt);
    }
    #pragma unroll
    for (int o = 16; o; o >>= 1) mx = fmaxf(mx, __shfl_xor_sync(0xffffffffu, mx, o));
    float sm = 0.f;
    for (int s = lane; s < cnt; s += 32) {
        float bt = si + sjb[nb[s]];
        bt = bt > 0.f ? bt : 0.2f*bt;
        sm += __expf(bt - mx);
    }
    #pragma unroll
    for (int o = 16; o; o >>= 1) sm += __shfl_xor_sync(0xffffffffu, sm, o);
    if (lane == 0) {
        g_mx  [warp] = (cnt > 0) ? mx : 0.f;
        g_invd[warp] = (cnt > 0) ? (1.f/sm) : 0.f;
    }
}

// ---------------- fused edge MLP (tensor core) + aggregate + GRU ----------------
// warp = node; 32-edge tiles; 3xTF32 split. Tile columns are permuted
// (c' = (c&3)*4 + (c>>2)) so a consumer lane's frag values for BOTH k-steps
// form one float4 -> 4 LDS.128 per phase instead of 16 LDS.32.
// lo is kept in registers (no hi readback).
__global__ void __launch_bounds__(256, 2) k_edge(
    const float* __restrict__ u0,
    const float* __restrict__ W1,
    const float* __restrict__ W2, const float* __restrict__ b2,
    const float* __restrict__ W3, const float* __restrict__ b3,
    const float* __restrict__ Wih, const float* __restrict__ bih, int t)
{
    __shared__ __align__(16) float2 sWfHi[8*4*32];   // 8 KB frag-ordered W2 hi
    __shared__ __align__(16) float2 sWfLo[8*4*32];   // 8 KB frag-ordered W2 lo
    __shared__ __align__(16) float  sT[8*32*20];     // 20 KB per-warp 32x20 tile
    __shared__ __align__(16) float  sA [8*NH1];
    __shared__ __align__(16) float  sw1e[NH1];
    __shared__ __align__(16) float  sSj[NN];
    __shared__ float sW3[NH2*FF];
    __shared__ float sb2[NH2], sb3[FF];
    __shared__ float s_si[8], s_mx[8], s_invd[8];
    __shared__ int   s_cnt[8];
    __shared__ float sWih[FF*24], sbih[24];
    __shared__ float sAl[8][32];
    __shared__ float sP[8][NH2];

    int tid = threadIdx.x;
    int bx  = blockIdx.x;
    int b   = bx >> 6;
    int i_base = (bx & 63) * 8;
    int rowbase = b*NN + i_base;

    for (int idx = tid; idx < 1024; idx += 256) {
        int ks  = idx >> 7;
        int nb4 = (idx >> 5) & 3;
        int ln  = idx & 31;
        int k0  = ks*8 + (ln & 3);
        int n   = nb4*8 + (ln >> 2);
        float w0 = W2[k0*NH2 + n];
        float w1 = W2[(k0+4)*NH2 + n];
        float h0 = tf32f(w0);
        float h1 = tf32f(w1);
        sWfHi[idx] = make_float2(h0, h1);
        sWfLo[idx] = make_float2(tf32f(w0 - h0), tf32f(w1 - h1));
    }
    for (int x = tid; x < NH2*FF; x += 256) sW3[x] = W3[x];
    if (tid < NH2) sb2[tid] = b2[tid];
    if (tid < FF)  sb3[tid] = b3[tid];
    if (tid < NH1) sw1e[tid] = W1[16*NH1 + tid];
    for (int x = tid; x < 8*NH1; x += 256) sA[x] = g_A[(size_t)rowbase*NH1 + x];
    if (tid < 8) {
        s_si  [tid] = g_si  [rowbase + tid];
        s_mx  [tid] = g_mx  [rowbase + tid];
        s_invd[tid] = g_invd[rowbase + tid];
        s_cnt [tid] = g_cnt [rowbase + tid];
    }
    for (int x = tid; x < NN; x += 256) sSj[x] = g_sj[b*NN + x];
    for (int x = tid; x < FF*24; x += 256) sWih[x] = Wih[x];
    if (tid < 24) sbih[tid] = bih[tid];
    __syncthreads();

    int w    = tid >> 5;
    int lane = tid & 31;
    int row  = rowbase + w;
    int cnt  = s_cnt[w];
    float si = s_si[w], mx = s_mx[w], invd = s_invd[w];
    const float4* sA4 = reinterpret_cast<const float4*>(&sA[w*NH1]);
    const float4* we4 = reinterpret_cast<const float4*>(sw1e);
    const unsigned short* nbp = g_nbr + (size_t)row*NN;
    const float* ec  = g_ec + (size_t)row*NN;
    float* tile = &sT[w*640];

    float pp[8];
    #pragma unroll
    for (int k = 0; k < 8; k++) pp[k] = 0.f;

    int r0 = lane >> 2, kq = lane & 3;
    int fb0 = r0*20 + kq*4;          // frag load bases (loop-invariant)
    int fb1 = (r0+8)*20 + kq*4;
    int fb2 = (r0+16)*20 + kq*4;
    int fb3 = (r0+24)*20 + kq*4;
    int ntile = (cnt + 31) >> 5;
    for (int tb = 0; tb < ntile; tb++) {
        int sb = tb << 5;
        int s = sb + lane;
        int valid = (s < cnt);
        int ss = valid ? s : sb;
        int j  = nbp[ss];
        int jb = b*NN + j;
        float e = valid ? ec[ss] : 0.f;
        {
            float bt = si + sSj[j];
            bt = bt > 0.f ? bt : 0.2f*bt;
            sAl[w][lane] = valid ? (__expf(bt - mx) * invd) : 0.f;
        }

        float acc0[16], acc1[16];
        #pragma unroll
        for (int k = 0; k < 16; k++) { acc0[k] = 0.f; acc1[k] = 0.f; }

        #pragma unroll 1
        for (int kc = 0; kc < 4; kc++) {
            // ---- phase A: h1 chunk, split hi/lo; store hi permuted, keep lo
            float x[16], lo[16];
            #pragma unroll
            for (int vv = 0; vv < 4; vv++) {
                int v = kc*4 + vv;
                float4 B = g_Bv[v*NBNN + jb];
                float4 A = sA4[v];
                float4 Wv = we4[v];
                x[4*vv+0] = fmaxf(A.x + fmaf(e, Wv.x, B.x), 0.f);
                x[4*vv+1] = fmaxf(A.y + fmaf(e, Wv.y, B.y), 0.f);
                x[4*vv+2] = fmaxf(A.z + fmaf(e, Wv.z, B.z), 0.f);
                x[4*vv+3] = fmaxf(A.w + fmaf(e, Wv.w, B.w), 0.f);
            }
            #pragma unroll
            for (int g = 0; g < 4; g++) {
                float h0 = tf32f(x[g]);
                float h1 = tf32f(x[g+4]);
                float h2 = tf32f(x[g+8]);
                float h3 = tf32f(x[g+12]);
                *reinterpret_cast<float4*>(&tile[lane*20 + g*4]) =
                    make_float4(h0, h1, h2, h3);
                lo[g]    = tf32f(x[g]    - h0);
                lo[g+4]  = tf32f(x[g+4]  - h1);
                lo[g+8]  = tf32f(x[g+8]  - h2);
                lo[g+12] = tf32f(x[g+12] - h3);
            }
            __syncwarp();

            // ---- hi MMAs: ahi*whi + ahi*wlo; whi cached for lo phase
            float whreg[2][4][2];
            {
                float4 f0 = *reinterpret_cast<float4*>(&tile[fb0]);
                float4 f1 = *reinterpret_cast<float4*>(&tile[fb1]);
                float4 f2 = *reinterpret_cast<float4*>(&tile[fb2]);
                float4 f3 = *reinterpret_cast<float4*>(&tile[fb3]);
                #pragma unroll
                for (int ks = 0; ks < 2; ks++) {
                    unsigned a0 = __float_as_uint(ks ? f0.z : f0.x);
                    unsigned a2 = __float_as_uint(ks ? f0.w : f0.y);
                    unsigned a1 = __float_as_uint(ks ? f1.z : f1.x);
                    unsigned a3 = __float_as_uint(ks ? f1.w : f1.y);
                    unsigned c0 = __float_as_uint(ks ? f2.z : f2.x);
                    unsigned c2 = __float_as_uint(ks ? f2.w : f2.y);
                    unsigned c1 = __float_as_uint(ks ? f3.z : f3.x);
                    unsigned c3 = __float_as_uint(ks ? f3.w : f3.y);
                    int kstep = kc*2 + ks;
                    #pragma unroll
                    for (int n4 = 0; n4 < 4; n4++) {
                        float2 wh = sWfHi[(kstep*4 + n4)*32 + lane];
                        float2 wl = sWfLo[(kstep*4 + n4)*32 + lane];
                        whreg[ks][n4][0] = wh.x; whreg[ks][n4][1] = wh.y;
                        unsigned bh0 = __float_as_uint(wh.x), bh1 = __float_as_uint(wh.y);
                        unsigned bl0 = __float_as_uint(wl.x), bl1 = __float_as_uint(wl.y);
                        MMA_TF32(acc0[4*n4+0], acc0[4*n4+1], acc0[4*n4+2], acc0[4*n4+3],
                                 a0, a1, a2, a3, bh0, bh1);
                        MMA_TF32(acc0[4*n4+0], acc0[4*n4+1], acc0[4*n4+2], acc0[4*n4+3],
                                 a0, a1, a2, a3, bl0, bl1);
                        MMA_TF32(acc1[4*n4+0], acc1[4*n4+1], acc1[4*n4+2], acc1[4*n4+3],
                                 c0, c1, c2, c3, bh0, bh1);
                        MMA_TF32(acc1[4*n4+0], acc1[4*n4+1], acc1[4*n4+2], acc1[4*n4+3],
                                 c0, c1, c2, c3, bl0, bl1);
                    }
                }
            }
            __syncwarp();

            // ---- store lo permuted (from regs; no readback)
            #pragma unroll
            for (int g = 0; g < 4; g++) {
                *reinterpret_cast<float4*>(&tile[lane*20 + g*4]) =
                    make_float4(lo[g], lo[g+4], lo[g+8], lo[g+12]);
            }
            __syncwarp();

            // ---- lo MMAs: alo*whi (whi from regs)
            {
                float4 f0 = *reinterpret_cast<float4*>(&tile[fb0]);
                float4 f1 = *reinterpret_cast<float4*>(&tile[fb1]);
                float4 f2 = *reinterpret_cast<float4*>(&tile[fb2]);
                float4 f3 = *reinterpret_cast<float4*>(&tile[fb3]);
                #pragma unroll
                for (int ks = 0; ks < 2; ks++) {
                    unsigned a0 = __float_as_uint(ks ? f0.z : f0.x);
                    unsigned a2 = __float_as_uint(ks ? f0.w : f0.y);
                    unsigned a1 = __float_as_uint(ks ? f1.z : f1.x);
                    unsigned a3 = __float_as_uint(ks ? f1.w : f1.y);
                    unsigned c0 = __float_as_uint(ks ? f2.z : f2.x);
                    unsigned c2 = __float_as_uint(ks ? f2.w : f2.y);
                    unsigned c1 = __float_as_uint(ks ? f3.z : f3.x);
                    unsigned c3 = __float_as_uint(ks ? f3.w : f3.y);
                    #pragma unroll
                    for (int n4 = 0; n4 < 4; n4++) {
                        unsigned bh0 = __float_as_uint(whreg[ks][n4][0]);
                        unsigned bh1 = __float_as_uint(whreg[ks][n4][1]);
                        MMA_TF32(acc0[4*n4+0], acc0[4*n4+1], acc0[4*n4+2], acc0[4*n4+3],
                                 a0, a1, a2, a3, bh0, bh1);
                        MMA_TF32(acc1[4*n4+0], acc1[4*n4+1], acc1[4*n4+2], acc1[4*n4+3],
                                 c0, c1, c2, c3, bh0, bh1);
                    }
                }
            }
            __syncwarp();
        }

        // ---- epilogue: bias + relu + alpha fold into pp
        float al0 = sAl[w][r0];
        float al1 = sAl[w][r0 + 8];
        float al2 = sAl[w][r0 + 16];
        float al3 = sAl[w][r0 + 24];
        #pragma unroll
        for (int n4 = 0; n4 < 4; n4++) {
            int c0 = n4*8 + 2*kq;
            float bza = sb2[c0], bzb = sb2[c0+1];
            pp[2*n4+0] += al0*fmaxf(acc0[4*n4+0] + bza, 0.f)
                        + al1*fmaxf(acc0[4*n4+2] + bza, 0.f)
                        + al2*fmaxf(acc1[4*n4+0] + bza, 0.f)
                        + al3*fmaxf(acc1[4*n4+2] + bza, 0.f);
            pp[2*n4+1] += al0*fmaxf(acc0[4*n4+1] + bzb, 0.f)
                        + al1*fmaxf(acc0[4*n4+3] + bzb, 0.f)
                        + al2*fmaxf(acc1[4*n4+1] + bzb, 0.f)
                        + al3*fmaxf(acc1[4*n4+3] + bzb, 0.f);
        }
        __syncwarp();
    }

    // reduce pp over lanes sharing the same kq column set
    #pragma unroll
    for (int o = 4; o <= 16; o <<= 1) {
        #pragma unroll
        for (int k = 0; k < 8; k++)
            pp[k] += __shfl_xor_sync(0xffffffffu, pp[k], o);
    }
    if (lane < 4) {
        #pragma unroll
        for (int n4 = 0; n4 < 4; n4++) {
            sP[w][n4*8 + 2*lane + 0] = pp[2*n4+0];
            sP[w][n4*8 + 2*lane + 1] = pp[2*n4+1];
        }
    }
    __syncwarp();

    // GRU update (lanes 0..7, lane = feature). agg = p @ W3 + b3*(cnt>0)
    if (lane < FF) {
        int f = lane;
        int node = row;
        float haveN = (cnt > 0) ? 1.f : 0.f;
        float acc = sb3[f] * haveN;
        #pragma unroll
        for (int k = 0; k < NH2; k++) acc = fmaf(sP[w][k], sW3[k*FF + f], acc);
        float agg_f = acc;

        float agg[FF];
        #pragma unroll
        for (int x = 0; x < FF; x++)
            agg[x] = __shfl_sync(0x000000ffu, agg_f, x);

        const float* uin  = (t == 0) ? u0 : g_u[t & 1];
        float*       uout = g_u[(t + 1) & 1];
        float uo = uin[node*FF + f];
        float gir = sbih[f], giz = sbih[f+8], gin = sbih[f+16];
        #pragma unroll
        for (int x = 0; x < FF; x++) {
            float ax = agg[x];
            gir = fmaf(ax, sWih[x*24 + f     ], gir);
            giz = fmaf(ax, sWih[x*24 + f +  8], giz);
            gin = fmaf(ax, sWih[x*24 + f + 16], gin);
        }
        float ghr = g_gh[(size_t)node*24 + f     ];
        float ghz = g_gh[(size_t)node*24 + f +  8];
        float ghn = g_gh[(size_t)node*24 + f + 16];
        float r  = 1.f/(1.f + __expf(-(gir + ghr)));
        float z  = 1.f/(1.f + __expf(-(giz + ghz)));
        float nn = tanhf(fmaf(r, ghn, gin));
        uout[node*FF + f] = (1.f - z)*nn + z*uo;
    }
}

// ---------------- readout ----------------
__global__ void k_readout(const float* __restrict__ W1, const float* __restrict__ b1,
                          const float* __restrict__ W2, const float* __restrict__ b2,
                          const float* __restrict__ W3, const float* __restrict__ b3,
                          float* __restrict__ out)
{
    __shared__ float sW1[FF*NH1], sb1[NH1], sW2[NH1*NH2], sb2[NH2], sW3[NH2*NS], sb3[NS];
    int tid = threadIdx.x;
    for (int x = tid; x < FF*NH1;  x += blockDim.x) sW1[x] = W1[x];
    for (int x = tid; x < NH1*NH2; x += blockDim.x) sW2[x] = W2[x];
    for (int x = tid; x < NH2*NS;  x += blockDim.x) sW3[x] = W3[x];
    if (tid < NH1) sb1[tid] = b1[tid];
    if (tid < NH2) sb2[tid] = b2[tid];
    if (tid < NS)  sb3[tid] = b3[tid];
    __syncthreads();

    int node = blockIdx.x * blockDim.x + tid;
    float u[FF];
    #pragma unroll
    for (int x = 0; x < FF; x++) u[x] = g_u[0][node*FF + x];

    float h2[NH2];
    #pragma unroll
    for (int k = 0; k < NH2; k++) h2[k] = sb2[k];
    for (int m = 0; m < NH1; m++) {
        float h1 = sb1[m];
        #pragma unroll
        for (int x = 0; x < FF; x++) h1 = fmaf(u[x], sW1[x*NH1 + m], h1);
        h1 = fmaxf(h1, 0.f);
        #pragma unroll
        for (int k = 0; k < NH2; k++) h2[k] = fmaf(h1, sW2[m*NH2 + k], h2[k]);
    }
    float l0 = sb3[0], l1 = sb3[1];
    #pragma unroll
    for (int k = 0; k < NH2; k++) {
        float x = fmaxf(h2[k], 0.f);
        l0 = fmaf(x, sW3[k*NS + 0], l0);
        l1 = fmaf(x, sW3[k*NS + 1], l1);
    }
    out[node*NS + 0] = l0;
    out[node*NS + 1] = l1;
}

// ---------------- launch ----------------
extern "C" void kernel_launch(void* const* d_in, const int* in_sizes, int n_in,
                              void* d_out, int out_size)
{
    (void)in_sizes; (void)n_in; (void)out_size;
    const float* u0     = (const float*)d_in[0];
    const int*   adj    = (const int*)  d_in[1];
    const float* ef     = (const float*)d_in[2];
    const float* sigma2 = (const float*)d_in[3];
    const float* Wattn  = (const float*)d_in[4];
    const float* al     = (const float*)d_in[5];
    const float* ar     = (const float*)d_in[6];
    const float* mW1    = (const float*)d_in[7];
    const float* mb1    = (const float*)d_in[8];
    const float* mW2    = (const float*)d_in[9];
    const float* mb2    = (const float*)d_in[10];
    const float* mW3    = (const float*)d_in[11];
    const float* mb3    = (const float*)d_in[12];
    const float* Wih    = (const float*)d_in[13];
    const float* Whh    = (const float*)d_in[14];
    const float* bih    = (const float*)d_in[15];
    const float* bhh    = (const float*)d_in[16];
    const float* rW1    = (const float*)d_in[17];
    const float* rb1    = (const float*)d_in[18];
    const float* rW2    = (const float*)d_in[19];
    const float* rb2    = (const float*)d_in[20];
    const float* rW3    = (const float*)d_in[21];
    const float* rb3    = (const float*)d_in[22];
    float* out = (float*)d_out;

    k_compact<<<NB*NN/4, 128>>>(adj, ef);
    for (int t = 0; t < TIT; t++) {
        k_node<<<32, 128>>>(u0, Wattn, al, ar, mW1, mb1, Whh, bhh, sigma2, t);
        k_soft<<<NB*NN/4, 128>>>();
        k_edge<<<NB*NN/8, 256>>>(u0, mW1, mW2, mb2, mW3, mb3, Wih, bih, t);
    }
    k_readout<<<32, 128>>>(rW1, rb1, rW2, rb2, rW3, rb3, out);
}

// round 15
// speedup vs baseline: 1.2043x; 1.2043x over previous
#include <cuda_runtime.h>
#include <math.h>

#define NB   8
#define NN   512
#define FF   8
#define FP   16
#define NH1  64
#define NH2  32
#define NS   2
#define TIT  10
#define NBNN (NB*NN)

// ---------------- scratch (no allocations allowed) ----------------
__device__ __align__(256) float  g_A  [NB*NN*NH1];   // u_i @ W1a + sigma*w1s + b1
__device__ __align__(256) float4 g_Bv [16*NB*NN];    // u_j @ W1b, v-major planes
__device__ __align__(256) float  g_si [NB*NN];
__device__ __align__(256) float  g_sj [NB*NN];
__device__ __align__(256) float  g_mx [NB*NN];
__device__ __align__(256) float  g_invd[NB*NN];
__device__ __align__(256) float  g_gh [NB*NN*24];
__device__ __align__(256) float  g_u  [2][NB*NN*FF];
__device__ __align__(256) unsigned short g_nbr[NB*NN*NN];
__device__ __align__(256) float  g_ec [NB*NN*NN];
__device__ __align__(256) int    g_cnt[NB*NN];

__device__ __forceinline__ unsigned tf32r(float x) {
    unsigned r; asm("cvt.rna.tf32.f32 %0, %1;" : "=r"(r) : "f"(x)); return r;
}
__device__ __forceinline__ float tf32f(float x) {
    return __uint_as_float(tf32r(x));
}
// exact tf32-representable "hi" part: zero the 13 mantissa bits tf32 ignores
__device__ __forceinline__ float tfmask(float x) {
    return __uint_as_float(__float_as_uint(x) & 0xffffe000u);
}

#define MMA_TF32(d0,d1,d2,d3,a0,a1,a2,a3,b0,b1) \
  asm("mma.sync.aligned.m16n8k8.row.col.f32.tf32.tf32.f32 " \
      "{%0,%1,%2,%3},{%4,%5,%6,%7},{%8,%9},{%0,%1,%2,%3};" \
      : "+f"(d0),"+f"(d1),"+f"(d2),"+f"(d3) \
      : "r"(a0),"r"(a1),"r"(a2),"r"(a3),"r"(b0),"r"(b1))

// ---------------- adjacency compaction ----------------
__global__ void k_compact(const int* __restrict__ adj, const float* __restrict__ ef)
{
    int warp = (blockIdx.x * blockDim.x + threadIdx.x) >> 5;
    int lane = threadIdx.x & 31;
    if (warp >= NB*NN) return;
    const int*   arow = adj + (size_t)warp * NN;
    const float* erow = ef  + (size_t)warp * NN;
    int base = 0;
    #pragma unroll
    for (int c = 0; c < NN/32; c++) {
        int jj = c*32 + lane;
        int a  = arow[jj];
        unsigned bal = __ballot_sync(0xffffffffu, a > 0);
        if (a > 0) {
            int pos = base + __popc(bal & ((1u << lane) - 1u));
            g_nbr[(size_t)warp*NN + pos] = (unsigned short)jj;
            g_ec [(size_t)warp*NN + pos] = erow[jj];
        }
        base += __popc(bal);
    }
    if (lane == 0) g_cnt[warp] = base;
}

// ---------------- per-node precompute ----------------
__global__ void k_node(const float* __restrict__ u0,
                       const float* __restrict__ Wattn,
                       const float* __restrict__ al, const float* __restrict__ ar,
                       const float* __restrict__ W1, const float* __restrict__ b1,
                       const float* __restrict__ Whh, const float* __restrict__ bhh,
                       const float* __restrict__ sigma2, int t)
{
    __shared__ float sWa[FF*FP], sal[FP], sar[FP];
    __shared__ float sW1a[FF*NH1], sW1b[FF*NH1], sw1s[NH1], sb1[NH1];
    __shared__ float sWhh[FF*24], sbhh[24];
    int tid = threadIdx.x;
    for (int x = tid; x < FF*FP; x += blockDim.x) sWa[x] = Wattn[x];
    if (tid < FP) { sal[tid] = al[tid]; sar[tid] = ar[tid]; }
    for (int x = tid; x < FF*NH1; x += blockDim.x) {
        sW1a[x] = W1[x];
        sW1b[x] = W1[FF*NH1 + x];
    }
    if (tid < NH1) { sw1s[tid] = W1[17*NH1 + tid]; sb1[tid] = b1[tid]; }
    for (int x = tid; x < FF*24; x += blockDim.x) sWhh[x] = Whh[x];
    if (tid < 24) sbhh[tid] = bhh[tid];
    __syncthreads();

    int node = blockIdx.x * blockDim.x + tid;
    int b = node >> 9;
    const float* uin = (t == 0) ? u0 : g_u[t & 1];
    float u[FF];
    #pragma unroll
    for (int x = 0; x < FF; x++) u[x] = uin[node*FF + x];
    float sg = sigma2[b];

    float si = 0.f, sj = 0.f;
    #pragma unroll
    for (int p = 0; p < FP; p++) {
        float acc = 0.f;
        #pragma unroll
        for (int x = 0; x < FF; x++) acc = fmaf(u[x], sWa[x*FP + p], acc);
        si = fmaf(acc, sal[p], si);
        sj = fmaf(acc, sar[p], sj);
    }
    g_si[node] = si; g_sj[node] = sj;

    float bb[NH1];
    for (int m = 0; m < NH1; m++) {
        float a  = fmaf(sg, sw1s[m], sb1[m]);
        float b2 = 0.f;
        #pragma unroll
        for (int x = 0; x < FF; x++) {
            a  = fmaf(u[x], sW1a[x*NH1 + m], a);
            b2 = fmaf(u[x], sW1b[x*NH1 + m], b2);
        }
        g_A[(size_t)node*NH1 + m] = a;
        bb[m] = b2;
    }
    #pragma unroll
    for (int v = 0; v < 16; v++)
        g_Bv[v*NBNN + node] = make_float4(bb[4*v+0], bb[4*v+1], bb[4*v+2], bb[4*v+3]);

    for (int g = 0; g < 24; g++) {
        float acc = sbhh[g];
        #pragma unroll
        for (int x = 0; x < FF; x++) acc = fmaf(u[x], sWhh[x*24 + g], acc);
        g_gh[(size_t)node*24 + g] = acc;
    }
}

// ---------------- softmax stats per row ----------------
__global__ void k_soft()
{
    int warp = (blockIdx.x * blockDim.x + threadIdx.x) >> 5;
    int lane = threadIdx.x & 31;
    if (warp >= NB*NN) return;
    int b = warp >> 9;
    int cnt = g_cnt[warp];
    float si = g_si[warp];
    const unsigned short* nb = g_nbr + (size_t)warp*NN;
    const float* sjb = g_sj + b*NN;

    float mx = -3.4e38f;
    for (int s = lane; s < cnt; s += 32) {
        float bt = si + sjb[nb[s]];
        bt = bt > 0.f ? bt : 0.2f*bt;
        mx = fmaxf(mx, bt);
    }
    #pragma unroll
    for (int o = 16; o; o >>= 1) mx = fmaxf(mx, __shfl_xor_sync(0xffffffffu, mx, o));
    float sm = 0.f;
    for (int s = lane; s < cnt; s += 32) {
        float bt = si + sjb[nb[s]];
        bt = bt > 0.f ? bt : 0.2f*bt;
        sm += __expf(bt - mx);
    }
    #pragma unroll
    for (int o = 16; o; o >>= 1) sm += __shfl_xor_sync(0xffffffffu, sm, o);
    if (lane == 0) {
        g_mx  [warp] = (cnt > 0) ? mx : 0.f;
        g_invd[warp] = (cnt > 0) ? (1.f/sm) : 0.f;
    }
}

// ---------------- fused edge MLP (tensor core) + aggregate + GRU ----------------
// warp = node; 32-edge tiles; 3xTF32 split with MASK-based hi (exact tf32) and
// raw-fp32 lo (HW truncation), so no cvt passes and no hi readback.
// Tile layout + frag loads identical to the verified round-13 build.
__global__ void __launch_bounds__(256, 2) k_edge(
    const float* __restrict__ u0,
    const float* __restrict__ W1,
    const float* __restrict__ W2, const float* __restrict__ b2,
    const float* __restrict__ W3, const float* __restrict__ b3,
    const float* __restrict__ Wih, const float* __restrict__ bih, int t)
{
    __shared__ __align__(16) float2 sWfHi[8*4*32];   // 8 KB frag-ordered W2 hi
    __shared__ __align__(16) float2 sWfLo[8*4*32];   // 8 KB frag-ordered W2 lo
    __shared__ __align__(16) float  sT[8*32*20];     // 20 KB per-warp 32x20 tile
    __shared__ __align__(16) float  sA [8*NH1];
    __shared__ __align__(16) float  sw1e[NH1];
    __shared__ __align__(16) float  sSj[NN];
    __shared__ float sW3[NH2*FF];
    __shared__ float sb2[NH2], sb3[FF];
    __shared__ float s_si[8], s_mx[8], s_invd[8];
    __shared__ int   s_cnt[8];
    __shared__ float sWih[FF*24], sbih[24];
    __shared__ float sAl[8][32];
    __shared__ float sP[8][NH2];

    int tid = threadIdx.x;
    int bx  = blockIdx.x;
    int b   = bx >> 6;
    int i_base = (bx & 63) * 8;
    int rowbase = b*NN + i_base;

    // frag-ordered W2 hi/lo (cvt-based; computed once, exact tf32 values)
    for (int idx = tid; idx < 1024; idx += 256) {
        int ks  = idx >> 7;
        int nb4 = (idx >> 5) & 3;
        int ln  = idx & 31;
        int k0  = ks*8 + (ln & 3);
        int n   = nb4*8 + (ln >> 2);
        float w0 = W2[k0*NH2 + n];
        float w1 = W2[(k0+4)*NH2 + n];
        float h0 = tf32f(w0);
        float h1 = tf32f(w1);
        sWfHi[idx] = make_float2(h0, h1);
        sWfLo[idx] = make_float2(tf32f(w0 - h0), tf32f(w1 - h1));
    }
    for (int x = tid; x < NH2*FF; x += 256) sW3[x] = W3[x];
    if (tid < NH2) sb2[tid] = b2[tid];
    if (tid < FF)  sb3[tid] = b3[tid];
    if (tid < NH1) sw1e[tid] = W1[16*NH1 + tid];
    for (int x = tid; x < 8*NH1; x += 256) sA[x] = g_A[(size_t)rowbase*NH1 + x];
    if (tid < 8) {
        s_si  [tid] = g_si  [rowbase + tid];
        s_mx  [tid] = g_mx  [rowbase + tid];
        s_invd[tid] = g_invd[rowbase + tid];
        s_cnt [tid] = g_cnt [rowbase + tid];
    }
    for (int x = tid; x < NN; x += 256) sSj[x] = g_sj[b*NN + x];
    for (int x = tid; x < FF*24; x += 256) sWih[x] = Wih[x];
    if (tid < 24) sbih[tid] = bih[tid];
    __syncthreads();

    int w    = tid >> 5;
    int lane = tid & 31;
    int row  = rowbase + w;
    int cnt  = s_cnt[w];
    float si = s_si[w], mx = s_mx[w], invd = s_invd[w];
    const float4* sA4 = reinterpret_cast<const float4*>(&sA[w*NH1]);
    const float4* we4 = reinterpret_cast<const float4*>(sw1e);
    const unsigned short* nbp = g_nbr + (size_t)row*NN;
    const float* ec  = g_ec + (size_t)row*NN;
    float* tile = &sT[w*640];

    float pp[8];
    #pragma unroll
    for (int k = 0; k < 8; k++) pp[k] = 0.f;

    int r0 = lane >> 2, kq = lane & 3;
    int ntile = (cnt + 31) >> 5;
    for (int tb = 0; tb < ntile; tb++) {
        int sb = tb << 5;
        int s = sb + lane;
        int valid = (s < cnt);
        int ss = valid ? s : sb;
        int j  = nbp[ss];
        int jb = b*NN + j;
        float e = valid ? ec[ss] : 0.f;
        {
            float bt = si + sSj[j];
            bt = bt > 0.f ? bt : 0.2f*bt;
            sAl[w][lane] = valid ? (__expf(bt - mx) * invd) : 0.f;
        }

        float acc0[16], acc1[16];
        #pragma unroll
        for (int k = 0; k < 16; k++) { acc0[k] = 0.f; acc1[k] = 0.f; }

        #pragma unroll 1
        for (int kc = 0; kc < 4; kc++) {
            // ---- phase A: h1 chunk; store hi = mask(x) (exact tf32 value)
            float x[16];
            #pragma unroll
            for (int vv = 0; vv < 4; vv++) {
                int v = kc*4 + vv;
                float4 B = g_Bv[v*NBNN + jb];
                float4 A = sA4[v];
                float4 Wv = we4[v];
                x[4*vv+0] = fmaxf(A.x + fmaf(e, Wv.x, B.x), 0.f);
                x[4*vv+1] = fmaxf(A.y + fmaf(e, Wv.y, B.y), 0.f);
                x[4*vv+2] = fmaxf(A.z + fmaf(e, Wv.z, B.z), 0.f);
                x[4*vv+3] = fmaxf(A.w + fmaf(e, Wv.w, B.w), 0.f);
            }
            #pragma unroll
            for (int c4 = 0; c4 < 4; c4++) {
                *reinterpret_cast<float4*>(&tile[lane*20 + 4*c4]) = make_float4(
                    tfmask(x[4*c4+0]), tfmask(x[4*c4+1]),
                    tfmask(x[4*c4+2]), tfmask(x[4*c4+3]));
            }
            __syncwarp();

            // ---- hi MMAs: ahi*whi + ahi*wlo; whi cached in regs for lo phase
            float whreg[2][4][2];
            #pragma unroll
            for (int ks = 0; ks < 2; ks++) {
                int kk = kq + ks*8;
                unsigned a0 = __float_as_uint(tile[r0*20 + kk]);
                unsigned a1 = __float_as_uint(tile[(r0+8)*20 + kk]);
                unsigned a2 = __float_as_uint(tile[r0*20 + kk + 4]);
                unsigned a3 = __float_as_uint(tile[(r0+8)*20 + kk + 4]);
                unsigned c0 = __float_as_uint(tile[(r0+16)*20 + kk]);
                unsigned c1 = __float_as_uint(tile[(r0+24)*20 + kk]);
                unsigned c2 = __float_as_uint(tile[(r0+16)*20 + kk + 4]);
                unsigned c3 = __float_as_uint(tile[(r0+24)*20 + kk + 4]);
                int kstep = kc*2 + ks;
                #pragma unroll
                for (int n4 = 0; n4 < 4; n4++) {
                    float2 wh = sWfHi[(kstep*4 + n4)*32 + lane];
                    float2 wl = sWfLo[(kstep*4 + n4)*32 + lane];
                    whreg[ks][n4][0] = wh.x; whreg[ks][n4][1] = wh.y;
                    unsigned bh0 = __float_as_uint(wh.x), bh1 = __float_as_uint(wh.y);
                    unsigned bl0 = __float_as_uint(wl.x), bl1 = __float_as_uint(wl.y);
                    MMA_TF32(acc0[4*n4+0], acc0[4*n4+1], acc0[4*n4+2], acc0[4*n4+3],
                             a0, a1, a2, a3, bh0, bh1);
                    MMA_TF32(acc0[4*n4+0], acc0[4*n4+1], acc0[4*n4+2], acc0[4*n4+3],
                             a0, a1, a2, a3, bl0, bl1);
                    MMA_TF32(acc1[4*n4+0], acc1[4*n4+1], acc1[4*n4+2], acc1[4*n4+3],
                             c0, c1, c2, c3, bh0, bh1);
                    MMA_TF32(acc1[4*n4+0], acc1[4*n4+1], acc1[4*n4+2], acc1[4*n4+3],
                             c0, c1, c2, c3, bl0, bl1);
                }
            }
            __syncwarp();

            // ---- overwrite tile with lo = x - mask(x) (exact; raw fp32,
            //      truncated to tf32 by the MMA hardware — error ~2^-20)
            #pragma unroll
            for (int c4 = 0; c4 < 4; c4++) {
                *reinterpret_cast<float4*>(&tile[lane*20 + 4*c4]) = make_float4(
                    x[4*c4+0] - tfmask(x[4*c4+0]), x[4*c4+1] - tfmask(x[4*c4+1]),
                    x[4*c4+2] - tfmask(x[4*c4+2]), x[4*c4+3] - tfmask(x[4*c4+3]));
            }
            __syncwarp();

            // ---- lo MMAs: alo*whi (whi from regs)
            #pragma unroll
            for (int ks = 0; ks < 2; ks++) {
                int kk = kq + ks*8;
                unsigned a0 = __float_as_uint(tile[r0*20 + kk]);
                unsigned a1 = __float_as_uint(tile[(r0+8)*20 + kk]);
                unsigned a2 = __float_as_uint(tile[r0*20 + kk + 4]);
                unsigned a3 = __float_as_uint(tile[(r0+8)*20 + kk + 4]);
                unsigned c0 = __float_as_uint(tile[(r0+16)*20 + kk]);
                unsigned c1 = __float_as_uint(tile[(r0+24)*20 + kk]);
                unsigned c2 = __float_as_uint(tile[(r0+16)*20 + kk + 4]);
                unsigned c3 = __float_as_uint(tile[(r0+24)*20 + kk + 4]);
                #pragma unroll
                for (int n4 = 0; n4 < 4; n4++) {
                    unsigned bh0 = __float_as_uint(whreg[ks][n4][0]);
                    unsigned bh1 = __float_as_uint(whreg[ks][n4][1]);
                    MMA_TF32(acc0[4*n4+0], acc0[4*n4+1], acc0[4*n4+2], acc0[4*n4+3],
                             a0, a1, a2, a3, bh0, bh1);
                    MMA_TF32(acc1[4*n4+0], acc1[4*n4+1], acc1[4*n4+2], acc1[4*n4+3],
                             c0, c1, c2, c3, bh0, bh1);
                }
            }
            __syncwarp();
        }

        // ---- epilogue: bias + relu + alpha fold into pp
        float al0 = sAl[w][r0];
        float al1 = sAl[w][r0 + 8];
        float al2 = sAl[w][r0 + 16];
        float al3 = sAl[w][r0 + 24];
        #pragma unroll
        for (int n4 = 0; n4 < 4; n4++) {
            int c0 = n4*8 + 2*kq;
            float bza = sb2[c0], bzb = sb2[c0+1];
            pp[2*n4+0] += al0*fmaxf(acc0[4*n4+0] + bza, 0.f)
                        + al1*fmaxf(acc0[4*n4+2] + bza, 0.f)
                        + al2*fmaxf(acc1[4*n4+0] + bza, 0.f)
                        + al3*fmaxf(acc1[4*n4+2] + bza, 0.f);
            pp[2*n4+1] += al0*fmaxf(acc0[4*n4+1] + bzb, 0.f)
                        + al1*fmaxf(acc0[4*n4+3] + bzb, 0.f)
                        + al2*fmaxf(acc1[4*n4+1] + bzb, 0.f)
                        + al3*fmaxf(acc1[4*n4+3] + bzb, 0.f);
        }
        __syncwarp();
    }

    // reduce pp over lanes sharing the same kq column set
    #pragma unroll
    for (int o = 4; o <= 16; o <<= 1) {
        #pragma unroll
        for (int k = 0; k < 8; k++)
            pp[k] += __shfl_xor_sync(0xffffffffu, pp[k], o);
    }
    if (lane < 4) {
        #pragma unroll
        for (int n4 = 0; n4 < 4; n4++) {
            sP[w][n4*8 + 2*lane + 0] = pp[2*n4+0];
            sP[w][n4*8 + 2*lane + 1] = pp[2*n4+1];
        }
    }
    __syncwarp();

    // GRU update (lanes 0..7, lane = feature). agg = p @ W3 + b3*(cnt>0)
    if (lane < FF) {
        int f = lane;
        int node = row;
        float haveN = (cnt > 0) ? 1.f : 0.f;
        float acc = sb3[f] * haveN;
        #pragma unroll
        for (int k = 0; k < NH2; k++) acc = fmaf(sP[w][k], sW3[k*FF + f], acc);
        float agg_f = acc;

        float agg[FF];
        #pragma unroll
        for (int x = 0; x < FF; x++)
            agg[x] = __shfl_sync(0x000000ffu, agg_f, x);

        const float* uin  = (t == 0) ? u0 : g_u[t & 1];
        float*       uout = g_u[(t + 1) & 1];
        float uo = uin[node*FF + f];
        float gir = sbih[f], giz = sbih[f+8], gin = sbih[f+16];
        #pragma unroll
        for (int x = 0; x < FF; x++) {
            float ax = agg[x];
            gir = fmaf(ax, sWih[x*24 + f     ], gir);
            giz = fmaf(ax, sWih[x*24 + f +  8], giz);
            gin = fmaf(ax, sWih[x*24 + f + 16], gin);
        }
        float ghr = g_gh[(size_t)node*24 + f     ];
        float ghz = g_gh[(size_t)node*24 + f +  8];
        float ghn = g_gh[(size_t)node*24 + f + 16];
        float r  = 1.f/(1.f + __expf(-(gir + ghr)));
        float z  = 1.f/(1.f + __expf(-(giz + ghz)));
        float nn = tanhf(fmaf(r, ghn, gin));
        uout[node*FF + f] = (1.f - z)*nn + z*uo;
    }
}

// ---------------- readout ----------------
__global__ void k_readout(const float* __restrict__ W1, const float* __restrict__ b1,
                          const float* __restrict__ W2, const float* __restrict__ b2,
                          const float* __restrict__ W3, const float* __restrict__ b3,
                          float* __restrict__ out)
{
    __shared__ float sW1[FF*NH1], sb1[NH1], sW2[NH1*NH2], sb2[NH2], sW3[NH2*NS], sb3[NS];
    int tid = threadIdx.x;
    for (int x = tid; x < FF*NH1;  x += blockDim.x) sW1[x] = W1[x];
    for (int x = tid; x < NH1*NH2; x += blockDim.x) sW2[x] = W2[x];
    for (int x = tid; x < NH2*NS;  x += blockDim.x) sW3[x] = W3[x];
    if (tid < NH1) sb1[tid] = b1[tid];
    if (tid < NH2) sb2[tid] = b2[tid];
    if (tid < NS)  sb3[tid] = b3[tid];
    __syncthreads();

    int node = blockIdx.x * blockDim.x + tid;
    float u[FF];
    #pragma unroll
    for (int x = 0; x < FF; x++) u[x] = g_u[0][node*FF + x];

    float h2[NH2];
    #pragma unroll
    for (int k = 0; k < NH2; k++) h2[k] = sb2[k];
    for (int m = 0; m < NH1; m++) {
        float h1 = sb1[m];
        #pragma unroll
        for (int x = 0; x < FF; x++) h1 = fmaf(u[x], sW1[x*NH1 + m], h1);
        h1 = fmaxf(h1, 0.f);
        #pragma unroll
        for (int k = 0; k < NH2; k++) h2[k] = fmaf(h1, sW2[m*NH2 + k], h2[k]);
    }
    float l0 = sb3[0], l1 = sb3[1];
    #pragma unroll
    for (int k = 0; k < NH2; k++) {
        float x = fmaxf(h2[k], 0.f);
        l0 = fmaf(x, sW3[k*NS + 0], l0);
        l1 = fmaf(x, sW3[k*NS + 1], l1);
    }
    out[node*NS + 0] = l0;
    out[node*NS + 1] = l1;
}

// ---------------- launch ----------------
extern "C" void kernel_launch(void* const* d_in, const int* in_sizes, int n_in,
                              void* d_out, int out_size)
{
    (void)in_sizes; (void)n_in; (void)out_size;
    const float* u0     = (const float*)d_in[0];
    const int*   adj    = (const int*)  d_in[1];
    const float* ef     = (const float*)d_in[2];
    const float* sigma2 = (const float*)d_in[3];
    const float* Wattn  = (const float*)d_in[4];
    const float* al     = (const float*)d_in[5];
    const float* ar     = (const float*)d_in[6];
    const float* mW1    = (const float*)d_in[7];
    const float* mb1    = (const float*)d_in[8];
    const float* mW2    = (const float*)d_in[9];
    const float* mb2    = (const float*)d_in[10];
    const float* mW3    = (const float*)d_in[11];
    const float* mb3    = (const float*)d_in[12];
    const float* Wih    = (const float*)d_in[13];
    const float* Whh    = (const float*)d_in[14];
    const float* bih    = (const float*)d_in[15];
    const float* bhh    = (const float*)d_in[16];
    const float* rW1    = (const float*)d_in[17];
    const float* rb1    = (const float*)d_in[18];
    const float* rW2    = (const float*)d_in[19];
    const float* rb2    = (const float*)d_in[20];
    const float* rW3    = (const float*)d_in[21];
    const float* rb3    = (const float*)d_in[22];
    float* out = (float*)d_out;

    k_compact<<<NB*NN/4, 128>>>(adj, ef);
    for (int t = 0; t < TIT; t++) {
        k_node<<<32, 128>>>(u0, Wattn, al, ar, mW1, mb1, Whh, bhh, sigma2, t);
        k_soft<<<NB*NN/4, 128>>>();
        k_edge<<<NB*NN/8, 256>>>(u0, mW1, mW2, mb2, mW3, mb3, Wih, bih, t);
    }
    k_readout<<<32, 128>>>(rW1, rb1, rW2, rb2, rW3, rb3, out);
}

// round 16
// speedup vs baseline: 1.6452x; 1.3661x over previous
#include <cuda_runtime.h>
#include <cuda_bf16.h>
#include <math.h>

#define NB   8
#define NN   512
#define FF   8
#define FP   16
#define NH1  64
#define NH2  32
#define NS   2
#define TIT  10
#define NBNN (NB*NN)

// ---------------- scratch (no allocations allowed) ----------------
__device__ __align__(256) float  g_A  [NB*NN*NH1];   // u_i @ W1a + sigma*w1s + b1
__device__ __align__(256) float4 g_Bv [16*NB*NN];    // u_j @ W1b, v-major planes
__device__ __align__(256) float  g_si [NB*NN];
__device__ __align__(256) float  g_sj [NB*NN];
__device__ __align__(256) float  g_mx [NB*NN];
__device__ __align__(256) float  g_invd[NB*NN];
__device__ __align__(256) float  g_gh [NB*NN*24];
__device__ __align__(256) float  g_u  [2][NB*NN*FF];
__device__ __align__(256) unsigned short g_nbr[NB*NN*NN];
__device__ __align__(256) float  g_ec [NB*NN*NN];
__device__ __align__(256) int    g_cnt[NB*NN];

// pack two floats to bf16x2 (round-to-nearest): low 16 bits = bf16(x0)
__device__ __forceinline__ unsigned pk2bf(float x0, float x1) {
    unsigned r;
    asm("cvt.rn.bf16x2.f32 %0, %1, %2;" : "=r"(r) : "f"(x1), "f"(x0));
    return r;
}
__device__ __forceinline__ float bflo_f(unsigned hp) {  // float of low bf16
    return __uint_as_float(hp << 16);
}
__device__ __forceinline__ float bfhi_f(unsigned hp) {  // float of high bf16
    return __uint_as_float(hp & 0xffff0000u);
}

#define MMA_BF16(d0,d1,d2,d3,a0,a1,a2,a3,b0,b1) \
  asm("mma.sync.aligned.m16n8k16.row.col.f32.bf16.bf16.f32 " \
      "{%0,%1,%2,%3},{%4,%5,%6,%7},{%8,%9},{%0,%1,%2,%3};" \
      : "+f"(d0),"+f"(d1),"+f"(d2),"+f"(d3) \
      : "r"(a0),"r"(a1),"r"(a2),"r"(a3),"r"(b0),"r"(b1))

// ---------------- adjacency compaction ----------------
__global__ void k_compact(const int* __restrict__ adj, const float* __restrict__ ef)
{
    int warp = (blockIdx.x * blockDim.x + threadIdx.x) >> 5;
    int lane = threadIdx.x & 31;
    if (warp >= NB*NN) return;
    const int*   arow = adj + (size_t)warp * NN;
    const float* erow = ef  + (size_t)warp * NN;
    int base = 0;
    #pragma unroll
    for (int c = 0; c < NN/32; c++) {
        int jj = c*32 + lane;
        int a  = arow[jj];
        unsigned bal = __ballot_sync(0xffffffffu, a > 0);
        if (a > 0) {
            int pos = base + __popc(bal & ((1u << lane) - 1u));
            g_nbr[(size_t)warp*NN + pos] = (unsigned short)jj;
            g_ec [(size_t)warp*NN + pos] = erow[jj];
        }
        base += __popc(bal);
    }
    if (lane == 0) g_cnt[warp] = base;
}

// ---------------- per-node precompute ----------------
__global__ void k_node(const float* __restrict__ u0,
                       const float* __restrict__ Wattn,
                       const float* __restrict__ al, const float* __restrict__ ar,
                       const float* __restrict__ W1, const float* __restrict__ b1,
                       const float* __restrict__ Whh, const float* __restrict__ bhh,
                       const float* __restrict__ sigma2, int t)
{
    __shared__ float sWa[FF*FP], sal[FP], sar[FP];
    __shared__ float sW1a[FF*NH1], sW1b[FF*NH1], sw1s[NH1], sb1[NH1];
    __shared__ float sWhh[FF*24], sbhh[24];
    int tid = threadIdx.x;
    for (int x = tid; x < FF*FP; x += blockDim.x) sWa[x] = Wattn[x];
    if (tid < FP) { sal[tid] = al[tid]; sar[tid] = ar[tid]; }
    for (int x = tid; x < FF*NH1; x += blockDim.x) {
        sW1a[x] = W1[x];
        sW1b[x] = W1[FF*NH1 + x];
    }
    if (tid < NH1) { sw1s[tid] = W1[17*NH1 + tid]; sb1[tid] = b1[tid]; }
    for (int x = tid; x < FF*24; x += blockDim.x) sWhh[x] = Whh[x];
    if (tid < 24) sbhh[tid] = bhh[tid];
    __syncthreads();

    int node = blockIdx.x * blockDim.x + tid;
    int b = node >> 9;
    const float* uin = (t == 0) ? u0 : g_u[t & 1];
    float u[FF];
    #pragma unroll
    for (int x = 0; x < FF; x++) u[x] = uin[node*FF + x];
    float sg = sigma2[b];

    float si = 0.f, sj = 0.f;
    #pragma unroll
    for (int p = 0; p < FP; p++) {
        float acc = 0.f;
        #pragma unroll
        for (int x = 0; x < FF; x++) acc = fmaf(u[x], sWa[x*FP + p], acc);
        si = fmaf(acc, sal[p], si);
        sj = fmaf(acc, sar[p], sj);
    }
    g_si[node] = si; g_sj[node] = sj;

    float bb[NH1];
    for (int m = 0; m < NH1; m++) {
        float a  = fmaf(sg, sw1s[m], sb1[m]);
        float b2 = 0.f;
        #pragma unroll
        for (int x = 0; x < FF; x++) {
            a  = fmaf(u[x], sW1a[x*NH1 + m], a);
            b2 = fmaf(u[x], sW1b[x*NH1 + m], b2);
        }
        g_A[(size_t)node*NH1 + m] = a;
        bb[m] = b2;
    }
    #pragma unroll
    for (int v = 0; v < 16; v++)
        g_Bv[v*NBNN + node] = make_float4(bb[4*v+0], bb[4*v+1], bb[4*v+2], bb[4*v+3]);

    for (int g = 0; g < 24; g++) {
        float acc = sbhh[g];
        #pragma unroll
        for (int x = 0; x < FF; x++) acc = fmaf(u[x], sWhh[x*24 + g], acc);
        g_gh[(size_t)node*24 + g] = acc;
    }
}

// ---------------- softmax stats per row ----------------
__global__ void k_soft()
{
    int warp = (blockIdx.x * blockDim.x + threadIdx.x) >> 5;
    int lane = threadIdx.x & 31;
    if (warp >= NB*NN) return;
    int b = warp >> 9;
    int cnt = g_cnt[warp];
    float si = g_si[warp];
    const unsigned short* nb = g_nbr + (size_t)warp*NN;
    const float* sjb = g_sj + b*NN;

    float mx = -3.4e38f;
    for (int s = lane; s < cnt; s += 32) {
        float bt = si + sjb[nb[s]];
        bt = bt > 0.f ? bt : 0.2f*bt;
        mx = fmaxf(mx, bt);
    }
    #pragma unroll
    for (int o = 16; o; o >>= 1) mx = fmaxf(mx, __shfl_xor_sync(0xffffffffu, mx, o));
    float sm = 0.f;
    for (int s = lane; s < cnt; s += 32) {
        float bt = si + sjb[nb[s]];
        bt = bt > 0.f ? bt : 0.2f*bt;
        sm += __expf(bt - mx);
    }
    #pragma unroll
    for (int o = 16; o; o >>= 1) sm += __shfl_xor_sync(0xffffffffu, sm, o);
    if (lane == 0) {
        g_mx  [warp] = (cnt > 0) ? mx : 0.f;
        g_invd[warp] = (cnt > 0) ? (1.f/sm) : 0.f;
    }
}

// ---------------- fused edge MLP (bf16 tensor core) + aggregate + GRU ----------------
// warp = node; 32-edge tiles; 3-term bf16 split (ahi*whi + ahi*wlo + alo*whi)
// with mma.m16n8k16 (half the k-steps / frag loads / MMAs of the tf32 build).
// Tile: 32 rows x 16 uint32 (bf16 pairs, low=even k), pad 20 (bank-conflict-free).
__global__ void __launch_bounds__(256, 2) k_edge(
    const float* __restrict__ u0,
    const float* __restrict__ W1,
    const float* __restrict__ W2, const float* __restrict__ b2,
    const float* __restrict__ W3, const float* __restrict__ b3,
    const float* __restrict__ Wih, const float* __restrict__ bih, int t)
{
    __shared__ __align__(16) uint2    sWfHi[4*4*32];  // 4 KB frag-ordered W2 hi (bf16x2)
    __shared__ __align__(16) uint2    sWfLo[4*4*32];  // 4 KB frag-ordered W2 lo
    __shared__ __align__(16) unsigned sT[8*32*20];    // 20 KB per-warp tile
    __shared__ __align__(16) float    sA [8*NH1];
    __shared__ __align__(16) float    sw1e[NH1];
    __shared__ __align__(16) float    sSj[NN];
    __shared__ float sW3[NH2*FF];
    __shared__ float sb2[NH2], sb3[FF];
    __shared__ float s_si[8], s_mx[8], s_invd[8];
    __shared__ int   s_cnt[8];
    __shared__ float sWih[FF*24], sbih[24];
    __shared__ float sAl[8][32];
    __shared__ float sP[8][NH2];

    int tid = threadIdx.x;
    int bx  = blockIdx.x;
    int b   = bx >> 6;
    int i_base = (bx & 63) * 8;
    int rowbase = b*NN + i_base;

    // frag-ordered W2 hi/lo (bf16 pairs). For (kstep,n4,lane):
    //   tg=lane&3, gid=lane>>2, n = n4*8+gid, kb = kstep*16 + tg*2
    //   b0 packs k = kb, kb+1 ; b1 packs k = kb+8, kb+9
    for (int idx = tid; idx < 512; idx += 256) {
        int kstep = idx >> 7;
        int nb4   = (idx >> 5) & 3;
        int ln    = idx & 31;
        int tg = ln & 3, gid = ln >> 2;
        int n  = nb4*8 + gid;
        int kb = kstep*16 + tg*2;
        float w00 = W2[kb*NH2 + n],     w01 = W2[(kb+1)*NH2 + n];
        float w08 = W2[(kb+8)*NH2 + n], w09 = W2[(kb+9)*NH2 + n];
        unsigned h0 = pk2bf(w00, w01);
        unsigned h1 = pk2bf(w08, w09);
        sWfHi[idx] = make_uint2(h0, h1);
        sWfLo[idx] = make_uint2(
            pk2bf(w00 - bflo_f(h0), w01 - bfhi_f(h0)),
            pk2bf(w08 - bflo_f(h1), w09 - bfhi_f(h1)));
    }
    for (int x = tid; x < NH2*FF; x += 256) sW3[x] = W3[x];
    if (tid < NH2) sb2[tid] = b2[tid];
    if (tid < FF)  sb3[tid] = b3[tid];
    if (tid < NH1) sw1e[tid] = W1[16*NH1 + tid];
    for (int x = tid; x < 8*NH1; x += 256) sA[x] = g_A[(size_t)rowbase*NH1 + x];
    if (tid < 8) {
        s_si  [tid] = g_si  [rowbase + tid];
        s_mx  [tid] = g_mx  [rowbase + tid];
        s_invd[tid] = g_invd[rowbase + tid];
        s_cnt [tid] = g_cnt [rowbase + tid];
    }
    for (int x = tid; x < NN; x += 256) sSj[x] = g_sj[b*NN + x];
    for (int x = tid; x < FF*24; x += 256) sWih[x] = Wih[x];
    if (tid < 24) sbih[tid] = bih[tid];
    __syncthreads();

    int w    = tid >> 5;
    int lane = tid & 31;
    int row  = rowbase + w;
    int cnt  = s_cnt[w];
    float si = s_si[w], mx = s_mx[w], invd = s_invd[w];
    const float4* sA4 = reinterpret_cast<const float4*>(&sA[w*NH1]);
    const float4* we4 = reinterpret_cast<const float4*>(sw1e);
    const unsigned short* nbp = g_nbr + (size_t)row*NN;
    const float* ec  = g_ec + (size_t)row*NN;
    unsigned* tile = &sT[w*640];

    float pp[8];
    #pragma unroll
    for (int k = 0; k < 8; k++) pp[k] = 0.f;

    int r0 = lane >> 2, kq = lane & 3;
    int ntile = (cnt + 31) >> 5;
    for (int tb = 0; tb < ntile; tb++) {
        int sb = tb << 5;
        int s = sb + lane;
        int valid = (s < cnt);
        int ss = valid ? s : sb;
        int j  = nbp[ss];
        int jb = b*NN + j;
        float e = valid ? ec[ss] : 0.f;
        {
            float bt = si + sSj[j];
            bt = bt > 0.f ? bt : 0.2f*bt;
            sAl[w][lane] = valid ? (__expf(bt - mx) * invd) : 0.f;
        }

        float acc0[16], acc1[16];
        #pragma unroll
        for (int k = 0; k < 16; k++) { acc0[k] = 0.f; acc1[k] = 0.f; }

        #pragma unroll 1
        for (int kc = 0; kc < 2; kc++) {
            // ---- phase A: 32 h1 values; pack hi to tile, keep lo packed in regs
            unsigned lop[16];
            {
                unsigned hip[16];
                #pragma unroll
                for (int g = 0; g < 8; g++) {
                    int v = kc*8 + g;
                    float4 B = g_Bv[v*NBNN + jb];
                    float4 A = sA4[v];
                    float4 Wv = we4[v];
                    float x0 = fmaxf(A.x + fmaf(e, Wv.x, B.x), 0.f);
                    float x1 = fmaxf(A.y + fmaf(e, Wv.y, B.y), 0.f);
                    float x2 = fmaxf(A.z + fmaf(e, Wv.z, B.z), 0.f);
                    float x3 = fmaxf(A.w + fmaf(e, Wv.w, B.w), 0.f);
                    unsigned hp0 = pk2bf(x0, x1);
                    unsigned hp1 = pk2bf(x2, x3);
                    hip[2*g]   = hp0;
                    hip[2*g+1] = hp1;
                    lop[2*g]   = pk2bf(x0 - bflo_f(hp0), x1 - bfhi_f(hp0));
                    lop[2*g+1] = pk2bf(x2 - bflo_f(hp1), x3 - bfhi_f(hp1));
                }
                uint4* tp = reinterpret_cast<uint4*>(&tile[lane*20]);
                tp[0] = make_uint4(hip[0],  hip[1],  hip[2],  hip[3]);
                tp[1] = make_uint4(hip[4],  hip[5],  hip[6],  hip[7]);
                tp[2] = make_uint4(hip[8],  hip[9],  hip[10], hip[11]);
                tp[3] = make_uint4(hip[12], hip[13], hip[14], hip[15]);
            }
            __syncwarp();

            // ---- hi MMAs: ahi*whi + ahi*wlo; whi cached in regs for lo phase
            unsigned whr[2][4][2];
            #pragma unroll
            for (int ks = 0; ks < 2; ks++) {
                int kk = ks*8 + kq;
                unsigned a0 = tile[r0*20 + kk];
                unsigned a1 = tile[(r0+8)*20 + kk];
                unsigned a2 = tile[r0*20 + kk + 4];
                unsigned a3 = tile[(r0+8)*20 + kk + 4];
                unsigned c0 = tile[(r0+16)*20 + kk];
                unsigned c1 = tile[(r0+24)*20 + kk];
                unsigned c2 = tile[(r0+16)*20 + kk + 4];
                unsigned c3 = tile[(r0+24)*20 + kk + 4];
                int kstep = kc*2 + ks;
                #pragma unroll
                for (int n4 = 0; n4 < 4; n4++) {
                    uint2 wh = sWfHi[(kstep*4 + n4)*32 + lane];
                    uint2 wl = sWfLo[(kstep*4 + n4)*32 + lane];
                    whr[ks][n4][0] = wh.x; whr[ks][n4][1] = wh.y;
                    MMA_BF16(acc0[4*n4+0], acc0[4*n4+1], acc0[4*n4+2], acc0[4*n4+3],
                             a0, a1, a2, a3, wh.x, wh.y);
                    MMA_BF16(acc0[4*n4+0], acc0[4*n4+1], acc0[4*n4+2], acc0[4*n4+3],
                             a0, a1, a2, a3, wl.x, wl.y);
                    MMA_BF16(acc1[4*n4+0], acc1[4*n4+1], acc1[4*n4+2], acc1[4*n4+3],
                             c0, c1, c2, c3, wh.x, wh.y);
                    MMA_BF16(acc1[4*n4+0], acc1[4*n4+1], acc1[4*n4+2], acc1[4*n4+3],
                             c0, c1, c2, c3, wl.x, wl.y);
                }
            }
            __syncwarp();

            // ---- store lo (from regs)
            {
                uint4* tp = reinterpret_cast<uint4*>(&tile[lane*20]);
                tp[0] = make_uint4(lop[0],  lop[1],  lop[2],  lop[3]);
                tp[1] = make_uint4(lop[4],  lop[5],  lop[6],  lop[7]);
                tp[2] = make_uint4(lop[8],  lop[9],  lop[10], lop[11]);
                tp[3] = make_uint4(lop[12], lop[13], lop[14], lop[15]);
            }
            __syncwarp();

            // ---- lo MMAs: alo*whi (whi from regs)
            #pragma unroll
            for (int ks = 0; ks < 2; ks++) {
                int kk = ks*8 + kq;
                unsigned a0 = tile[r0*20 + kk];
                unsigned a1 = tile[(r0+8)*20 + kk];
                unsigned a2 = tile[r0*20 + kk + 4];
                unsigned a3 = tile[(r0+8)*20 + kk + 4];
                unsigned c0 = tile[(r0+16)*20 + kk];
                unsigned c1 = tile[(r0+24)*20 + kk];
                unsigned c2 = tile[(r0+16)*20 + kk + 4];
                unsigned c3 = tile[(r0+24)*20 + kk + 4];
                #pragma unroll
                for (int n4 = 0; n4 < 4; n4++) {
                    MMA_BF16(acc0[4*n4+0], acc0[4*n4+1], acc0[4*n4+2], acc0[4*n4+3],
                             a0, a1, a2, a3, whr[ks][n4][0], whr[ks][n4][1]);
                    MMA_BF16(acc1[4*n4+0], acc1[4*n4+1], acc1[4*n4+2], acc1[4*n4+3],
                             c0, c1, c2, c3, whr[ks][n4][0], whr[ks][n4][1]);
                }
            }
            __syncwarp();
        }

        // ---- epilogue: bias + relu + alpha fold into pp (C layout = m16n8)
        float al0 = sAl[w][r0];
        float al1 = sAl[w][r0 + 8];
        float al2 = sAl[w][r0 + 16];
        float al3 = sAl[w][r0 + 24];
        #pragma unroll
        for (int n4 = 0; n4 < 4; n4++) {
            int c0 = n4*8 + 2*kq;
            float bza = sb2[c0], bzb = sb2[c0+1];
            pp[2*n4+0] += al0*fmaxf(acc0[4*n4+0] + bza, 0.f)
                        + al1*fmaxf(acc0[4*n4+2] + bza, 0.f)
                        + al2*fmaxf(acc1[4*n4+0] + bza, 0.f)
                        + al3*fmaxf(acc1[4*n4+2] + bza, 0.f);
            pp[2*n4+1] += al0*fmaxf(acc0[4*n4+1] + bzb, 0.f)
                        + al1*fmaxf(acc0[4*n4+3] + bzb, 0.f)
                        + al2*fmaxf(acc1[4*n4+1] + bzb, 0.f)
                        + al3*fmaxf(acc1[4*n4+3] + bzb, 0.f);
        }
        __syncwarp();
    }

    // reduce pp over lanes sharing the same kq column set
    #pragma unroll
    for (int o = 4; o <= 16; o <<= 1) {
        #pragma unroll
        for (int k = 0; k < 8; k++)
            pp[k] += __shfl_xor_sync(0xffffffffu, pp[k], o);
    }
    if (lane < 4) {
        #pragma unroll
        for (int n4 = 0; n4 < 4; n4++) {
            sP[w][n4*8 + 2*lane + 0] = pp[2*n4+0];
            sP[w][n4*8 + 2*lane + 1] = pp[2*n4+1];
        }
    }
    __syncwarp();

    // GRU update (lanes 0..7, lane = feature). agg = p @ W3 + b3*(cnt>0)
    if (lane < FF) {
        int f = lane;
        int node = row;
        float haveN = (cnt > 0) ? 1.f : 0.f;
        float acc = sb3[f] * haveN;
        #pragma unroll
        for (int k = 0; k < NH2; k++) acc = fmaf(sP[w][k], sW3[k*FF + f], acc);
        float agg_f = acc;

        float agg[FF];
        #pragma unroll
        for (int x = 0; x < FF; x++)
            agg[x] = __shfl_sync(0x000000ffu, agg_f, x);

        const float* uin  = (t == 0) ? u0 : g_u[t & 1];
        float*       uout = g_u[(t + 1) & 1];
        float uo = uin[node*FF + f];
        float gir = sbih[f], giz = sbih[f+8], gin = sbih[f+16];
        #pragma unroll
        for (int x = 0; x < FF; x++) {
            float ax = agg[x];
            gir = fmaf(ax, sWih[x*24 + f     ], gir);
            giz = fmaf(ax, sWih[x*24 + f +  8], giz);
            gin = fmaf(ax, sWih[x*24 + f + 16], gin);
        }
        float ghr = g_gh[(size_t)node*24 + f     ];
        float ghz = g_gh[(size_t)node*24 + f +  8];
        float ghn = g_gh[(size_t)node*24 + f + 16];
        float r  = 1.f/(1.f + __expf(-(gir + ghr)));
        float z  = 1.f/(1.f + __expf(-(giz + ghz)));
        float nn = tanhf(fmaf(r, ghn, gin));
        uout[node*FF + f] = (1.f - z)*nn + z*uo;
    }
}

// ---------------- readout ----------------
__global__ void k_readout(const float* __restrict__ W1, const float* __restrict__ b1,
                          const float* __restrict__ W2, const float* __restrict__ b2,
                          const float* __restrict__ W3, const float* __restrict__ b3,
                          float* __restrict__ out)
{
    __shared__ float sW1[FF*NH1], sb1[NH1], sW2[NH1*NH2], sb2[NH2], sW3[NH2*NS], sb3[NS];
    int tid = threadIdx.x;
    for (int x = tid; x < FF*NH1;  x += blockDim.x) sW1[x] = W1[x];
    for (int x = tid; x < NH1*NH2; x += blockDim.x) sW2[x] = W2[x];
    for (int x = tid; x < NH2*NS;  x += blockDim.x) sW3[x] = W3[x];
    if (tid < NH1) sb1[tid] = b1[tid];
    if (tid < NH2) sb2[tid] = b2[tid];
    if (tid < NS)  sb3[tid] = b3[tid];
    __syncthreads();

    int node = blockIdx.x * blockDim.x + tid;
    float u[FF];
    #pragma unroll
    for (int x = 0; x < FF; x++) u[x] = g_u[0][node*FF + x];

    float h2[NH2];
    #pragma unroll
    for (int k = 0; k < NH2; k++) h2[k] = sb2[k];
    for (int m = 0; m < NH1; m++) {
        float h1 = sb1[m];
        #pragma unroll
        for (int x = 0; x < FF; x++) h1 = fmaf(u[x], sW1[x*NH1 + m], h1);
        h1 = fmaxf(h1, 0.f);
        #pragma unroll
        for (int k = 0; k < NH2; k++) h2[k] = fmaf(h1, sW2[m*NH2 + k], h2[k]);
    }
    float l0 = sb3[0], l1 = sb3[1];
    #pragma unroll
    for (int k = 0; k < NH2; k++) {
        float x = fmaxf(h2[k], 0.f);
        l0 = fmaf(x, sW3[k*NS + 0], l0);
        l1 = fmaf(x, sW3[k*NS + 1], l1);
    }
    out[node*NS + 0] = l0;
    out[node*NS + 1] = l1;
}

// ---------------- launch ----------------
extern "C" void kernel_launch(void* const* d_in, const int* in_sizes, int n_in,
                              void* d_out, int out_size)
{
    (void)in_sizes; (void)n_in; (void)out_size;
    const float* u0     = (const float*)d_in[0];
    const int*   adj    = (const int*)  d_in[1];
    const float* ef     = (const float*)d_in[2];
    const float* sigma2 = (const float*)d_in[3];
    const float* Wattn  = (const float*)d_in[4];
    const float* al     = (const float*)d_in[5];
    const float* ar     = (const float*)d_in[6];
    const float* mW1    = (const float*)d_in[7];
    const float* mb1    = (const float*)d_in[8];
    const float* mW2    = (const float*)d_in[9];
    const float* mb2    = (const float*)d_in[10];
    const float* mW3    = (const float*)d_in[11];
    const float* mb3    = (const float*)d_in[12];
    const float* Wih    = (const float*)d_in[13];
    const float* Whh    = (const float*)d_in[14];
    const float* bih    = (const float*)d_in[15];
    const float* bhh    = (const float*)d_in[16];
    const float* rW1    = (const float*)d_in[17];
    const float* rb1    = (const float*)d_in[18];
    const float* rW2    = (const float*)d_in[19];
    const float* rb2    = (const float*)d_in[20];
    const float* rW3    = (const float*)d_in[21];
    const float* rb3    = (const float*)d_in[22];
    float* out = (float*)d_out;

    k_compact<<<NB*NN/4, 128>>>(adj, ef);
    for (int t = 0; t < TIT; t++) {
        k_node<<<32, 128>>>(u0, Wattn, al, ar, mW1, mb1, Whh, bhh, sigma2, t);
        k_soft<<<NB*NN/4, 128>>>();
        k_edge<<<NB*NN/8, 256>>>(u0, mW1, mW2, mb2, mW3, mb3, Wih, bih, t);
    }
    k_readout<<<32, 128>>>(rW1, rb1, rW2, rb2, rW3, rb3, out);
}